// round 2
// baseline (speedup 1.0000x reference)
#include <cuda_runtime.h>
#include <math.h>

// ---------------- problem constants ----------------
#define BB 256
#define SS 128
#define HH 768
#define NHH 8
#define HDD 96
// qkv row stride = 3*H = 2304

// ---------------- scratch (static device globals; no runtime alloc) ----------------
__device__ float g_qkv[75497472];      // 32768 * 2304  (302 MB)
__device__ float g_scores[33554432];   // 2048 * 128 * 128 (128 MB)
__device__ float g_abar[BB * HH];
__device__ float g_seqr[BB * HH];
__device__ float g_bufA[BB * 1536];
__device__ float g_bufB[BB * 1536];
__device__ float g_d1o[BB * 384];

// ---------------- tf32 helpers ----------------
__device__ __forceinline__ unsigned f2tf(float x) {
    unsigned r;
    asm("cvt.rna.tf32.f32 %0, %1;" : "=r"(r) : "f"(x));
    return r;
}

// ---------------- fused tf32x2 (3-pass) GEMM:  C[m,n] = sum_k A[m,k] * W[n,k] ----------------
// Near-fp32 accuracy: for each operand x, hi = tf32(x), lo = tf32(x - hi);
// accumulate hi*hi + hi*lo + lo*hi (lo*lo ~2^-22, dropped).
// Block tile 128x128, K-tile 32, 256 threads, warps 2x4, each warp 64x32 (4x4 m16n8k8 tiles).
// z-batch: offA = (z/zdiv)*sA1 + (z%zdiv)*sA2  (same for W); offC = z*sC.
__global__ void __launch_bounds__(256) gemm_tf32x2_k(
    const float* __restrict__ A, int lda, long sA1, long sA2,
    const float* __restrict__ W, int ldw, long sW1, long sW2,
    const float* __restrict__ bias, float* __restrict__ C, int ldc, long sC,
    int K, int zdiv)
{
    __shared__ float As[128 * 36];   // padded stride 36 -> conflict-free frag loads, float4-aligned
    __shared__ float Bs[128 * 36];

    int z = blockIdx.z;
    const float* Ab = A + (long)(z / zdiv) * sA1 + (long)(z % zdiv) * sA2 + (long)blockIdx.y * 128 * lda;
    const float* Wb = W + (long)(z / zdiv) * sW1 + (long)(z % zdiv) * sW2 + (long)blockIdx.x * 128 * ldw;
    float* Cb = C + (long)z * sC + (long)blockIdx.y * 128 * ldc + blockIdx.x * 128;

    int tid = threadIdx.x, warp = tid >> 5, lane = tid & 31;
    int wm = warp >> 2, wn = warp & 3;     // 2 x 4 warp grid
    int g = lane >> 2, t = lane & 3;       // groupID, threadID_in_group

    float acc[4][4][4];
#pragma unroll
    for (int i = 0; i < 4; i++)
#pragma unroll
        for (int j = 0; j < 4; j++)
#pragma unroll
            for (int e = 0; e < 4; e++) acc[i][j][e] = 0.0f;

    for (int k0 = 0; k0 < K; k0 += 32) {
        // cooperative loads: 128 rows x 32 cols per tile, 4 float4 per thread each (fp32, no convert)
#pragma unroll
        for (int i = 0; i < 4; i++) {
            int idx = tid + i * 256;             // 0..1023
            int row = idx >> 3, c4 = (idx & 7) * 4;
            *(float4*)(&As[row * 36 + c4]) = *(const float4*)(Ab + (long)row * lda + k0 + c4);
            *(float4*)(&Bs[row * 36 + c4]) = *(const float4*)(Wb + (long)row * ldw + k0 + c4);
        }
        __syncthreads();

#pragma unroll
        for (int ks = 0; ks < 4; ks++) {
            int c0 = ks * 8 + t;

            // B fragments: split into hi/lo once per ks
            unsigned bh[4][2], bl[4][2];
#pragma unroll
            for (int nt = 0; nt < 4; nt++) {
                int n0 = wn * 32 + nt * 8 + g;
                float b0 = Bs[n0 * 36 + c0];
                float b1 = Bs[n0 * 36 + c0 + 4];
                bh[nt][0] = f2tf(b0); bl[nt][0] = f2tf(b0 - __uint_as_float(bh[nt][0]));
                bh[nt][1] = f2tf(b1); bl[nt][1] = f2tf(b1 - __uint_as_float(bh[nt][1]));
            }

#pragma unroll
            for (int mt = 0; mt < 4; mt++) {
                int r0 = wm * 64 + mt * 16 + g;
                float a0 = As[r0 * 36 + c0];
                float a1 = As[(r0 + 8) * 36 + c0];
                float a2 = As[r0 * 36 + c0 + 4];
                float a3 = As[(r0 + 8) * 36 + c0 + 4];
                unsigned ah[4], al[4];
                ah[0] = f2tf(a0); al[0] = f2tf(a0 - __uint_as_float(ah[0]));
                ah[1] = f2tf(a1); al[1] = f2tf(a1 - __uint_as_float(ah[1]));
                ah[2] = f2tf(a2); al[2] = f2tf(a2 - __uint_as_float(ah[2]));
                ah[3] = f2tf(a3); al[3] = f2tf(a3 - __uint_as_float(ah[3]));

#pragma unroll
                for (int nt = 0; nt < 4; nt++) {
                    // cross terms first, then hi*hi (order-independent sum)
                    asm("mma.sync.aligned.m16n8k8.row.col.f32.tf32.tf32.f32 "
                        "{%0,%1,%2,%3},{%4,%5,%6,%7},{%8,%9},{%0,%1,%2,%3};"
                        : "+f"(acc[mt][nt][0]), "+f"(acc[mt][nt][1]),
                          "+f"(acc[mt][nt][2]), "+f"(acc[mt][nt][3])
                        : "r"(ah[0]), "r"(ah[1]), "r"(ah[2]), "r"(ah[3]),
                          "r"(bl[nt][0]), "r"(bl[nt][1]));
                    asm("mma.sync.aligned.m16n8k8.row.col.f32.tf32.tf32.f32 "
                        "{%0,%1,%2,%3},{%4,%5,%6,%7},{%8,%9},{%0,%1,%2,%3};"
                        : "+f"(acc[mt][nt][0]), "+f"(acc[mt][nt][1]),
                          "+f"(acc[mt][nt][2]), "+f"(acc[mt][nt][3])
                        : "r"(al[0]), "r"(al[1]), "r"(al[2]), "r"(al[3]),
                          "r"(bh[nt][0]), "r"(bh[nt][1]));
                    asm("mma.sync.aligned.m16n8k8.row.col.f32.tf32.tf32.f32 "
                        "{%0,%1,%2,%3},{%4,%5,%6,%7},{%8,%9},{%0,%1,%2,%3};"
                        : "+f"(acc[mt][nt][0]), "+f"(acc[mt][nt][1]),
                          "+f"(acc[mt][nt][2]), "+f"(acc[mt][nt][3])
                        : "r"(ah[0]), "r"(ah[1]), "r"(ah[2]), "r"(ah[3]),
                          "r"(bh[nt][0]), "r"(bh[nt][1]));
                }
            }
        }
        __syncthreads();
    }

    // epilogue: C = acc (+bias)
#pragma unroll
    for (int mt = 0; mt < 4; mt++) {
        int r0 = wm * 64 + mt * 16 + g;
#pragma unroll
        for (int nt = 0; nt < 4; nt++) {
            int c = wn * 32 + nt * 8 + 2 * t;
            float b0 = 0.f, b1 = 0.f;
            if (bias) { b0 = bias[blockIdx.x * 128 + c]; b1 = bias[blockIdx.x * 128 + c + 1]; }
            float* p0 = Cb + (long)r0 * ldc + c;
            float* p1 = Cb + (long)(r0 + 8) * ldc + c;
            p0[0] = acc[mt][nt][0] + b0; p0[1] = acc[mt][nt][1] + b1;
            p1[0] = acc[mt][nt][2] + b0; p1[1] = acc[mt][nt][3] + b1;
        }
    }
}

// ---------------- attention: softmax row-mean + GEMV (per head) ----------------
// abar[b, h*96+d] = sum_k ((1/S) sum_s attn[s,k]) * v[k,d]
__global__ void attn_kernel(const float* __restrict__ scores,
                            const float* __restrict__ qkv,
                            float* __restrict__ abar)
{
    __shared__ float wa[4][128];
    int bh = blockIdx.x;
    int b = bh >> 3, h = bh & 7;
    int tid = threadIdx.x, warp = tid >> 5, lane = tid & 31;

#pragma unroll
    for (int j = 0; j < 4; j++) wa[warp][lane + 32 * j] = 0.0f;

    const float* sc = scores + (long)bh * 16384;
    const float scale = 0.10206207261596577f;  // 1/sqrt(96)

    for (int s = warp; s < 128; s += 4) {
        float x0 = sc[s * 128 + lane] * scale;
        float x1 = sc[s * 128 + lane + 32] * scale;
        float x2 = sc[s * 128 + lane + 64] * scale;
        float x3 = sc[s * 128 + lane + 96] * scale;
        float m = fmaxf(fmaxf(x0, x1), fmaxf(x2, x3));
#pragma unroll
        for (int o = 16; o; o >>= 1) m = fmaxf(m, __shfl_xor_sync(0xffffffffu, m, o));
        float e0 = expf(x0 - m), e1 = expf(x1 - m), e2 = expf(x2 - m), e3 = expf(x3 - m);
        float sm = e0 + e1 + e2 + e3;
#pragma unroll
        for (int o = 16; o; o >>= 1) sm += __shfl_xor_sync(0xffffffffu, sm, o);
        float inv = 1.0f / sm;
        wa[warp][lane]      += e0 * inv;
        wa[warp][lane + 32] += e1 * inv;
        wa[warp][lane + 64] += e2 * inv;
        wa[warp][lane + 96] += e3 * inv;
    }
    __syncthreads();
    if (warp == 0) {
#pragma unroll
        for (int j = 0; j < 4; j++) {
            int c = lane + 32 * j;
            wa[0][c] = wa[0][c] + wa[1][c] + wa[2][c] + wa[3][c];
        }
    }
    __syncthreads();

    if (tid < 96) {
        const float* v = qkv + (long)b * SS * 2304 + 1536 + h * 96 + tid;
        float acc = 0.0f;
#pragma unroll 8
        for (int k = 0; k < 128; k++) acc = fmaf(wa[0][k], v[(long)k * 2304], acc);
        abar[b * HH + h * 96 + tid] = acc * (1.0f / 128.0f);
    }
}

// ---------------- fused LayerNorm + exact GELU ----------------
__global__ void ln_gelu_k(const float* __restrict__ in, const float* __restrict__ gm,
                          const float* __restrict__ be, float* __restrict__ out, int N)
{
    int row = blockIdx.x;
    const float* x = in + (long)row * N;
    float* y = out + (long)row * N;
    int tid = threadIdx.x, warp = tid >> 5, lane = tid & 31;

    float s = 0.f, s2 = 0.f;
    for (int i = tid; i < N; i += blockDim.x) { float v = x[i]; s += v; s2 += v * v; }
#pragma unroll
    for (int o = 16; o; o >>= 1) { s += __shfl_xor_sync(0xffffffffu, s, o); s2 += __shfl_xor_sync(0xffffffffu, s2, o); }
    __shared__ float rs[8], rs2[8], sm_mean, sm_rstd;
    if (lane == 0) { rs[warp] = s; rs2[warp] = s2; }
    __syncthreads();
    if (tid == 0) {
        float S = 0.f, S2 = 0.f;
        for (int w = 0; w < 8; w++) { S += rs[w]; S2 += rs2[w]; }
        float mean = S / N;
        float var = S2 / N - mean * mean;
        sm_mean = mean;
        sm_rstd = rsqrtf(var + 1e-5f);
    }
    __syncthreads();
    float mean = sm_mean, rstd = sm_rstd;
    for (int i = tid; i < N; i += blockDim.x) {
        float v = (x[i] - mean) * rstd * gm[i] + be[i];
        y[i] = 0.5f * v * (1.0f + erff(v * 0.70710678118654752f));
    }
}

// ---------------- warp dot helper ----------------
__device__ __forceinline__ float warp_dot(const float* a, const float* b, int n, int lane)
{
    float s = 0.f;
    for (int i = lane; i < n; i += 32) s = fmaf(a[i], b[i], s);
#pragma unroll
    for (int o = 16; o; o >>= 1) s += __shfl_xor_sync(0xffffffffu, s, o);
    return s;
}

// ---------------- small 5-way head (domain logits) ----------------
__global__ void head5_kernel(const float* __restrict__ in, int Kin,
                             const float* __restrict__ w, const float* __restrict__ bias,
                             float* __restrict__ out)
{
    int b = blockIdx.x, warp = threadIdx.x >> 5, lane = threadIdx.x & 31;
    if (warp < 5) {
        float s = warp_dot(in + (long)b * Kin, w + (long)warp * Kin, Kin, lane);
        if (lane == 0) out[b * 5 + warp] = s + bias[warp];
    }
}

// ---------------- gating softmax + top-2 + expert mix ----------------
__global__ void gate_kernel(const float* __restrict__ r1o,
                            const float* __restrict__ w_r2, const float* __restrict__ b_r2,
                            const float* __restrict__ hs,
                            const float* __restrict__ w_e, const float* __restrict__ b_e,
                            float* __restrict__ out)
{
    __shared__ float gl[5], ae[10];
    int b = blockIdx.x, tid = threadIdx.x, warp = tid >> 5, lane = tid & 31;

    if (warp < 5) {
        float s = warp_dot(r1o + (long)b * 384, w_r2 + (long)warp * 384, 384, lane);
        if (lane == 0) gl[warp] = s + b_r2[warp];
    }
    const float* cls = hs + (long)b * SS * HH;
    for (int idx = warp; idx < 10; idx += 8) {
        float s = warp_dot(cls, w_e + (long)idx * HH, HH, lane);
        if (lane == 0) ae[idx] = s + b_e[idx];
    }
    __syncthreads();

    if (tid == 0) {
        float m = gl[0];
        for (int j = 1; j < 5; j++) m = fmaxf(m, gl[j]);
        float e[5], sum = 0.f;
        for (int j = 0; j < 5; j++) { e[j] = expf(gl[j] - m); sum += e[j]; }
        float p[5];
        for (int j = 0; j < 5; j++) { p[j] = e[j] / sum; out[512 + b * 5 + j] = p[j]; }
        // top-2 (first-max on ties, matching jax.lax.top_k)
        int i1 = 0;
        for (int j = 1; j < 5; j++) if (p[j] > p[i1]) i1 = j;
        int i2 = -1;
        for (int j = 0; j < 5; j++) if (j != i1 && (i2 < 0 || p[j] > p[i2])) i2 = j;
        float ps = p[i1] + p[i2];
        float w1 = p[i1] / ps, w2 = p[i2] / ps;
        for (int ee = 0; ee < 5; ee++) {
            bool sel = (ee == i1) || (ee == i2);
            out[1792 + b * 10 + ee * 2 + 0] = sel ? ae[ee * 2 + 0] : 0.0f;
            out[1792 + b * 10 + ee * 2 + 1] = sel ? ae[ee * 2 + 1] : 0.0f;
        }
        out[b * 2 + 0] = w1 * ae[i1 * 2 + 0] + w2 * ae[i2 * 2 + 0];
        out[b * 2 + 1] = w1 * ae[i1 * 2 + 1] + w2 * ae[i2 * 2 + 1];
    }
}

// ---------------- host launcher ----------------
extern "C" void kernel_launch(void* const* d_in, const int* in_sizes, int n_in,
                              void* d_out, int out_size)
{
    const float* hs    = (const float*)d_in[0];
    const float* w_qkv = (const float*)d_in[1];
    const float* b_qkv = (const float*)d_in[2];
    const float* w_out = (const float*)d_in[3];
    const float* b_out = (const float*)d_in[4];
    const float* w_f1  = (const float*)d_in[5];
    const float* b_f1  = (const float*)d_in[6];
    const float* gf1   = (const float*)d_in[7];
    const float* bef1  = (const float*)d_in[8];
    const float* w_f2  = (const float*)d_in[9];
    const float* b_f2  = (const float*)d_in[10];
    const float* gf2   = (const float*)d_in[11];
    const float* bef2  = (const float*)d_in[12];
    const float* w_c   = (const float*)d_in[13];
    const float* b_c   = (const float*)d_in[14];
    const float* gc    = (const float*)d_in[15];
    const float* bec   = (const float*)d_in[16];
    const float* w_r1  = (const float*)d_in[17];
    const float* b_r1  = (const float*)d_in[18];
    const float* gr1   = (const float*)d_in[19];
    const float* ber1  = (const float*)d_in[20];
    const float* w_r2  = (const float*)d_in[21];
    const float* b_r2  = (const float*)d_in[22];
    const float* w_d1  = (const float*)d_in[23];
    const float* b_d1  = (const float*)d_in[24];
    const float* gd1   = (const float*)d_in[25];
    const float* bed1  = (const float*)d_in[26];
    const float* w_d2  = (const float*)d_in[27];
    const float* b_d2  = (const float*)d_in[28];
    const float* w_e   = (const float*)d_in[29];
    const float* b_e   = (const float*)d_in[30];
    float* out = (float*)d_out;

    float *qkv, *scores, *abar, *seqr, *bufA, *bufB, *d1o;
    cudaGetSymbolAddress((void**)&qkv,    g_qkv);
    cudaGetSymbolAddress((void**)&scores, g_scores);
    cudaGetSymbolAddress((void**)&abar,   g_abar);
    cudaGetSymbolAddress((void**)&seqr,   g_seqr);
    cudaGetSymbolAddress((void**)&bufA,   g_bufA);
    cudaGetSymbolAddress((void**)&bufB,   g_bufB);
    cudaGetSymbolAddress((void**)&d1o,    g_d1o);

    // --- qkv = hs @ w_qkv.T + b_qkv  (tf32x2; M=32768, N=2304, K=768) ---
    gemm_tf32x2_k<<<dim3(2304 / 128, 32768 / 128, 1), 256>>>(
        hs, HH, 0, 0, w_qkv, HH, 0, 0, b_qkv, qkv, 2304, 0, HH, 1);

    // --- scores[b,h] = q @ k^T  (batched over 2048 heads; M=N=128, K=96) ---
    gemm_tf32x2_k<<<dim3(1, 1, BB * NHH), 256>>>(
        qkv, 2304, (long)SS * 2304, 96,
        qkv + 768, 2304, (long)SS * 2304, 96,
        nullptr, scores, 128, (long)SS * SS, HDD, NHH);

    // --- softmax row-mean + GEMV -> abar (B, H) ---
    attn_kernel<<<BB * NHH, 128>>>(scores, qkv, abar);

    auto gemm = [&](const float* A, int lda, const float* W, const float* bias,
                    float* C, int N, int K) {
        dim3 grid(N / 128, BB / 128, 1);
        gemm_tf32x2_k<<<grid, 256>>>(A, lda, 0, 0, W, K, 0, 0, bias, C, N, 0, K, 1);
    };

    // --- seq_repr = abar @ w_out.T + b_out  (exact: mean commutes with linear) ---
    gemm(abar, HH, w_out, b_out, seqr, HH, HH);

    // --- f1 -> f2 -> ctx -> r1 chain ---
    gemm(seqr, HH, w_f1, b_f1, bufA, 1536, HH);
    ln_gelu_k<<<BB, 256>>>(bufA, gf1, bef1, bufB, 1536);

    gemm(bufB, 1536, w_f2, b_f2, bufA, 1536, 1536);
    ln_gelu_k<<<BB, 256>>>(bufA, gf2, bef2, bufB, 1536);

    gemm(bufB, 1536, w_c, b_c, bufA, HH, 1536);
    ln_gelu_k<<<BB, 256>>>(bufA, gc, bec, bufB, HH);

    gemm(bufB, HH, w_r1, b_r1, bufA, 384, HH);
    ln_gelu_k<<<BB, 256>>>(bufA, gr1, ber1, bufB, 384);   // bufB = r1o (256 x 384)

    // --- domain path (cls rows of hidden, lda = S*H) ---
    gemm(hs, SS * HH, w_d1, b_d1, bufA, 384, HH);
    ln_gelu_k<<<BB, 256>>>(bufA, gd1, bed1, d1o, 384);
    head5_kernel<<<BB, 160>>>(d1o, 384, w_d2, b_d2, out + 4352);

    // --- gating softmax + top-2 + expert logits / final logits ---
    gate_kernel<<<BB, 256>>>(bufB, w_r2, b_r2, hs, w_e, b_e, out);

    (void)in_sizes; (void)n_in; (void)out_size;
}

// round 3
// speedup vs baseline: 1.1472x; 1.1472x over previous
#include <cuda_runtime.h>
#include <math.h>

// ---------------- problem constants ----------------
#define BB 256
#define SS 128
#define HH 768
#define NHH 8
#define HDD 96
// qkv row stride = 3*H = 2304

// ---------------- scratch (static device globals; no runtime alloc) ----------------
__device__ float g_qkv[75497472];      // 32768 * 2304  (302 MB)
__device__ float g_scores[33554432];   // 2048 * 128 * 128 (128 MB)
__device__ float g_abar[BB * HH];
__device__ float g_seqr[BB * HH];
__device__ float g_bufA[BB * 1536];
__device__ float g_bufB[BB * 1536];
__device__ float g_d1o[BB * 384];

// ---------------- tf32 helpers ----------------
__device__ __forceinline__ unsigned f2tf(float x) {
    unsigned r;
    asm("cvt.rna.tf32.f32 %0, %1;" : "=r"(r) : "f"(x));
    return r;
}

// ---------------- fused tf32x2 (3-pass) GEMM:  C[m,n] = sum_k A[m,k] * W[n,k] ----------------
// Near-fp32 accuracy: hi = tf32(x), lo = tf32(x - hi); accumulate hi*lo + lo*hi + hi*hi.
// Key structure (R3): hi/lo split happens ONCE per element at smem-store time; the
// inner loop is pure LDS + MMA. Global loads for tile t+1 are register-staged while
// computing tile t.
// Block tile 128x128, K-tile 32, 256 threads, warps 2x4, each warp 64x32 (4x4 m16n8k8 tiles).
// z-batch: offA = (z/zdiv)*sA1 + (z%zdiv)*sA2  (same for W); offC = z*sC.
__global__ void __launch_bounds__(256) gemm_tf32x2_k(
    const float* __restrict__ A, int lda, long sA1, long sA2,
    const float* __restrict__ W, int ldw, long sW1, long sW2,
    const float* __restrict__ bias, float* __restrict__ C, int ldc, long sC,
    int K, int zdiv)
{
    extern __shared__ float sm[];
    float* Ah = sm;            // 128 * 36
    float* Al = sm + 4608;
    float* Bh = sm + 9216;
    float* Bl = sm + 13824;    // total 4 * 4608 * 4B = 73728 B

    int z = blockIdx.z;
    const float* Ab = A + (long)(z / zdiv) * sA1 + (long)(z % zdiv) * sA2 + (long)blockIdx.y * 128 * lda;
    const float* Wb = W + (long)(z / zdiv) * sW1 + (long)(z % zdiv) * sW2 + (long)blockIdx.x * 128 * ldw;
    float* Cb = C + (long)z * sC + (long)blockIdx.y * 128 * ldc + blockIdx.x * 128;

    int tid = threadIdx.x, warp = tid >> 5, lane = tid & 31;
    int wm = warp >> 2, wn = warp & 3;     // 2 x 4 warp grid
    int g = lane >> 2, t = lane & 31 & 3;  // groupID, threadID_in_group

    // per-thread cooperative-load coordinates (4 float4 per operand per tile)
    int lrow[4], lcol[4];
#pragma unroll
    for (int i = 0; i < 4; i++) {
        int idx = tid + i * 256;           // 0..1023
        lrow[i] = idx >> 3;
        lcol[i] = (idx & 7) * 4;
    }

    float acc[4][4][4];
#pragma unroll
    for (int i = 0; i < 4; i++)
#pragma unroll
        for (int j = 0; j < 4; j++)
#pragma unroll
            for (int e = 0; e < 4; e++) acc[i][j][e] = 0.0f;

    // prologue: stage tile 0 in registers
    float4 ra[4], rb[4];
#pragma unroll
    for (int i = 0; i < 4; i++) {
        ra[i] = *(const float4*)(Ab + (long)lrow[i] * lda + lcol[i]);
        rb[i] = *(const float4*)(Wb + (long)lrow[i] * ldw + lcol[i]);
    }

    for (int k0 = 0; k0 < K; k0 += 32) {
        // store staged tile to smem, splitting hi/lo exactly once per element
#pragma unroll
        for (int i = 0; i < 4; i++) {
            int ad = lrow[i] * 36 + lcol[i];
            float4 v = ra[i];
            float4 h, l;
            h.x = __uint_as_float(f2tf(v.x)); l.x = __uint_as_float(f2tf(v.x - h.x));
            h.y = __uint_as_float(f2tf(v.y)); l.y = __uint_as_float(f2tf(v.y - h.y));
            h.z = __uint_as_float(f2tf(v.z)); l.z = __uint_as_float(f2tf(v.z - h.z));
            h.w = __uint_as_float(f2tf(v.w)); l.w = __uint_as_float(f2tf(v.w - h.w));
            *(float4*)(&Ah[ad]) = h;
            *(float4*)(&Al[ad]) = l;
            v = rb[i];
            h.x = __uint_as_float(f2tf(v.x)); l.x = __uint_as_float(f2tf(v.x - h.x));
            h.y = __uint_as_float(f2tf(v.y)); l.y = __uint_as_float(f2tf(v.y - h.y));
            h.z = __uint_as_float(f2tf(v.z)); l.z = __uint_as_float(f2tf(v.z - h.z));
            h.w = __uint_as_float(f2tf(v.w)); l.w = __uint_as_float(f2tf(v.w - h.w));
            *(float4*)(&Bh[ad]) = h;
            *(float4*)(&Bl[ad]) = l;
        }
        __syncthreads();

        // prefetch next tile into registers (overlaps with compute below)
        if (k0 + 32 < K) {
#pragma unroll
            for (int i = 0; i < 4; i++) {
                ra[i] = *(const float4*)(Ab + (long)lrow[i] * lda + k0 + 32 + lcol[i]);
                rb[i] = *(const float4*)(Wb + (long)lrow[i] * ldw + k0 + 32 + lcol[i]);
            }
        }

        // pure LDS + MMA inner loop
#pragma unroll
        for (int ks = 0; ks < 4; ks++) {
            int c0 = ks * 8 + t;

            unsigned bhf[4][2], blf[4][2];
#pragma unroll
            for (int nt = 0; nt < 4; nt++) {
                int n0 = wn * 32 + nt * 8 + g;
                bhf[nt][0] = __float_as_uint(Bh[n0 * 36 + c0]);
                bhf[nt][1] = __float_as_uint(Bh[n0 * 36 + c0 + 4]);
                blf[nt][0] = __float_as_uint(Bl[n0 * 36 + c0]);
                blf[nt][1] = __float_as_uint(Bl[n0 * 36 + c0 + 4]);
            }

#pragma unroll
            for (int mt = 0; mt < 4; mt++) {
                int r0 = wm * 64 + mt * 16 + g;
                unsigned ah[4], al[4];
                ah[0] = __float_as_uint(Ah[r0 * 36 + c0]);
                ah[1] = __float_as_uint(Ah[(r0 + 8) * 36 + c0]);
                ah[2] = __float_as_uint(Ah[r0 * 36 + c0 + 4]);
                ah[3] = __float_as_uint(Ah[(r0 + 8) * 36 + c0 + 4]);
                al[0] = __float_as_uint(Al[r0 * 36 + c0]);
                al[1] = __float_as_uint(Al[(r0 + 8) * 36 + c0]);
                al[2] = __float_as_uint(Al[r0 * 36 + c0 + 4]);
                al[3] = __float_as_uint(Al[(r0 + 8) * 36 + c0 + 4]);

#pragma unroll
                for (int nt = 0; nt < 4; nt++) {
                    asm("mma.sync.aligned.m16n8k8.row.col.f32.tf32.tf32.f32 "
                        "{%0,%1,%2,%3},{%4,%5,%6,%7},{%8,%9},{%0,%1,%2,%3};"
                        : "+f"(acc[mt][nt][0]), "+f"(acc[mt][nt][1]),
                          "+f"(acc[mt][nt][2]), "+f"(acc[mt][nt][3])
                        : "r"(ah[0]), "r"(ah[1]), "r"(ah[2]), "r"(ah[3]),
                          "r"(blf[nt][0]), "r"(blf[nt][1]));
                    asm("mma.sync.aligned.m16n8k8.row.col.f32.tf32.tf32.f32 "
                        "{%0,%1,%2,%3},{%4,%5,%6,%7},{%8,%9},{%0,%1,%2,%3};"
                        : "+f"(acc[mt][nt][0]), "+f"(acc[mt][nt][1]),
                          "+f"(acc[mt][nt][2]), "+f"(acc[mt][nt][3])
                        : "r"(al[0]), "r"(al[1]), "r"(al[2]), "r"(al[3]),
                          "r"(bhf[nt][0]), "r"(bhf[nt][1]));
                    asm("mma.sync.aligned.m16n8k8.row.col.f32.tf32.tf32.f32 "
                        "{%0,%1,%2,%3},{%4,%5,%6,%7},{%8,%9},{%0,%1,%2,%3};"
                        : "+f"(acc[mt][nt][0]), "+f"(acc[mt][nt][1]),
                          "+f"(acc[mt][nt][2]), "+f"(acc[mt][nt][3])
                        : "r"(ah[0]), "r"(ah[1]), "r"(ah[2]), "r"(ah[3]),
                          "r"(bhf[nt][0]), "r"(bhf[nt][1]));
                }
            }
        }
        __syncthreads();
    }

    // epilogue: C = acc (+bias)
#pragma unroll
    for (int mt = 0; mt < 4; mt++) {
        int r0 = wm * 64 + mt * 16 + g;
#pragma unroll
        for (int nt = 0; nt < 4; nt++) {
            int c = wn * 32 + nt * 8 + 2 * t;
            float b0 = 0.f, b1 = 0.f;
            if (bias) { b0 = bias[blockIdx.x * 128 + c]; b1 = bias[blockIdx.x * 128 + c + 1]; }
            float* p0 = Cb + (long)r0 * ldc + c;
            float* p1 = Cb + (long)(r0 + 8) * ldc + c;
            p0[0] = acc[mt][nt][0] + b0; p0[1] = acc[mt][nt][1] + b1;
            p1[0] = acc[mt][nt][2] + b0; p1[1] = acc[mt][nt][3] + b1;
        }
    }
}

#define GEMM_SMEM 73728

// ---------------- attention: softmax row-mean + GEMV (per head) ----------------
// abar[b, h*96+d] = sum_k ((1/S) sum_s attn[s,k]) * v[k,d]
__global__ void attn_kernel(const float* __restrict__ scores,
                            const float* __restrict__ qkv,
                            float* __restrict__ abar)
{
    __shared__ float wa[4][128];
    int bh = blockIdx.x;
    int b = bh >> 3, h = bh & 7;
    int tid = threadIdx.x, warp = tid >> 5, lane = tid & 31;

#pragma unroll
    for (int j = 0; j < 4; j++) wa[warp][lane + 32 * j] = 0.0f;

    const float* sc = scores + (long)bh * 16384;
    const float scale = 0.10206207261596577f;  // 1/sqrt(96)

    for (int s = warp; s < 128; s += 4) {
        float x0 = sc[s * 128 + lane] * scale;
        float x1 = sc[s * 128 + lane + 32] * scale;
        float x2 = sc[s * 128 + lane + 64] * scale;
        float x3 = sc[s * 128 + lane + 96] * scale;
        float m = fmaxf(fmaxf(x0, x1), fmaxf(x2, x3));
#pragma unroll
        for (int o = 16; o; o >>= 1) m = fmaxf(m, __shfl_xor_sync(0xffffffffu, m, o));
        float e0 = expf(x0 - m), e1 = expf(x1 - m), e2 = expf(x2 - m), e3 = expf(x3 - m);
        float sm = e0 + e1 + e2 + e3;
#pragma unroll
        for (int o = 16; o; o >>= 1) sm += __shfl_xor_sync(0xffffffffu, sm, o);
        float inv = 1.0f / sm;
        wa[warp][lane]      += e0 * inv;
        wa[warp][lane + 32] += e1 * inv;
        wa[warp][lane + 64] += e2 * inv;
        wa[warp][lane + 96] += e3 * inv;
    }
    __syncthreads();
    if (warp == 0) {
#pragma unroll
        for (int j = 0; j < 4; j++) {
            int c = lane + 32 * j;
            wa[0][c] = wa[0][c] + wa[1][c] + wa[2][c] + wa[3][c];
        }
    }
    __syncthreads();

    if (tid < 96) {
        const float* v = qkv + (long)b * SS * 2304 + 1536 + h * 96 + tid;
        float acc = 0.0f;
#pragma unroll 8
        for (int k = 0; k < 128; k++) acc = fmaf(wa[0][k], v[(long)k * 2304], acc);
        abar[b * HH + h * 96 + tid] = acc * (1.0f / 128.0f);
    }
}

// ---------------- fused LayerNorm + exact GELU ----------------
__global__ void ln_gelu_k(const float* __restrict__ in, const float* __restrict__ gm,
                          const float* __restrict__ be, float* __restrict__ out, int N)
{
    int row = blockIdx.x;
    const float* x = in + (long)row * N;
    float* y = out + (long)row * N;
    int tid = threadIdx.x, warp = tid >> 5, lane = tid & 31;

    float s = 0.f, s2 = 0.f;
    for (int i = tid; i < N; i += blockDim.x) { float v = x[i]; s += v; s2 += v * v; }
#pragma unroll
    for (int o = 16; o; o >>= 1) { s += __shfl_xor_sync(0xffffffffu, s, o); s2 += __shfl_xor_sync(0xffffffffu, s2, o); }
    __shared__ float rs[8], rs2[8], sm_mean, sm_rstd;
    if (lane == 0) { rs[warp] = s; rs2[warp] = s2; }
    __syncthreads();
    if (tid == 0) {
        float S = 0.f, S2 = 0.f;
        for (int w = 0; w < 8; w++) { S += rs[w]; S2 += rs2[w]; }
        float mean = S / N;
        float var = S2 / N - mean * mean;
        sm_mean = mean;
        sm_rstd = rsqrtf(var + 1e-5f);
    }
    __syncthreads();
    float mean = sm_mean, rstd = sm_rstd;
    for (int i = tid; i < N; i += blockDim.x) {
        float v = (x[i] - mean) * rstd * gm[i] + be[i];
        y[i] = 0.5f * v * (1.0f + erff(v * 0.70710678118654752f));
    }
}

// ---------------- warp dot helper ----------------
__device__ __forceinline__ float warp_dot(const float* a, const float* b, int n, int lane)
{
    float s = 0.f;
    for (int i = lane; i < n; i += 32) s = fmaf(a[i], b[i], s);
#pragma unroll
    for (int o = 16; o; o >>= 1) s += __shfl_xor_sync(0xffffffffu, s, o);
    return s;
}

// ---------------- small 5-way head (domain logits) ----------------
__global__ void head5_kernel(const float* __restrict__ in, int Kin,
                             const float* __restrict__ w, const float* __restrict__ bias,
                             float* __restrict__ out)
{
    int b = blockIdx.x, warp = threadIdx.x >> 5, lane = threadIdx.x & 31;
    if (warp < 5) {
        float s = warp_dot(in + (long)b * Kin, w + (long)warp * Kin, Kin, lane);
        if (lane == 0) out[b * 5 + warp] = s + bias[warp];
    }
}

// ---------------- gating softmax + top-2 + expert mix ----------------
__global__ void gate_kernel(const float* __restrict__ r1o,
                            const float* __restrict__ w_r2, const float* __restrict__ b_r2,
                            const float* __restrict__ hs,
                            const float* __restrict__ w_e, const float* __restrict__ b_e,
                            float* __restrict__ out)
{
    __shared__ float gl[5], ae[10];
    int b = blockIdx.x, tid = threadIdx.x, warp = tid >> 5, lane = tid & 31;

    if (warp < 5) {
        float s = warp_dot(r1o + (long)b * 384, w_r2 + (long)warp * 384, 384, lane);
        if (lane == 0) gl[warp] = s + b_r2[warp];
    }
    const float* cls = hs + (long)b * SS * HH;
    for (int idx = warp; idx < 10; idx += 8) {
        float s = warp_dot(cls, w_e + (long)idx * HH, HH, lane);
        if (lane == 0) ae[idx] = s + b_e[idx];
    }
    __syncthreads();

    if (tid == 0) {
        float m = gl[0];
        for (int j = 1; j < 5; j++) m = fmaxf(m, gl[j]);
        float e[5], sum = 0.f;
        for (int j = 0; j < 5; j++) { e[j] = expf(gl[j] - m); sum += e[j]; }
        float p[5];
        for (int j = 0; j < 5; j++) { p[j] = e[j] / sum; out[512 + b * 5 + j] = p[j]; }
        // top-2 (first-max on ties, matching jax.lax.top_k)
        int i1 = 0;
        for (int j = 1; j < 5; j++) if (p[j] > p[i1]) i1 = j;
        int i2 = -1;
        for (int j = 0; j < 5; j++) if (j != i1 && (i2 < 0 || p[j] > p[i2])) i2 = j;
        float ps = p[i1] + p[i2];
        float w1 = p[i1] / ps, w2 = p[i2] / ps;
        for (int ee = 0; ee < 5; ee++) {
            bool sel = (ee == i1) || (ee == i2);
            out[1792 + b * 10 + ee * 2 + 0] = sel ? ae[ee * 2 + 0] : 0.0f;
            out[1792 + b * 10 + ee * 2 + 1] = sel ? ae[ee * 2 + 1] : 0.0f;
        }
        out[b * 2 + 0] = w1 * ae[i1 * 2 + 0] + w2 * ae[i2 * 2 + 0];
        out[b * 2 + 1] = w1 * ae[i1 * 2 + 1] + w2 * ae[i2 * 2 + 1];
    }
}

// ---------------- host launcher ----------------
extern "C" void kernel_launch(void* const* d_in, const int* in_sizes, int n_in,
                              void* d_out, int out_size)
{
    const float* hs    = (const float*)d_in[0];
    const float* w_qkv = (const float*)d_in[1];
    const float* b_qkv = (const float*)d_in[2];
    const float* w_out = (const float*)d_in[3];
    const float* b_out = (const float*)d_in[4];
    const float* w_f1  = (const float*)d_in[5];
    const float* b_f1  = (const float*)d_in[6];
    const float* gf1   = (const float*)d_in[7];
    const float* bef1  = (const float*)d_in[8];
    const float* w_f2  = (const float*)d_in[9];
    const float* b_f2  = (const float*)d_in[10];
    const float* gf2   = (const float*)d_in[11];
    const float* bef2  = (const float*)d_in[12];
    const float* w_c   = (const float*)d_in[13];
    const float* b_c   = (const float*)d_in[14];
    const float* gc    = (const float*)d_in[15];
    const float* bec   = (const float*)d_in[16];
    const float* w_r1  = (const float*)d_in[17];
    const float* b_r1  = (const float*)d_in[18];
    const float* gr1   = (const float*)d_in[19];
    const float* ber1  = (const float*)d_in[20];
    const float* w_r2  = (const float*)d_in[21];
    const float* b_r2  = (const float*)d_in[22];
    const float* w_d1  = (const float*)d_in[23];
    const float* b_d1  = (const float*)d_in[24];
    const float* gd1   = (const float*)d_in[25];
    const float* bed1  = (const float*)d_in[26];
    const float* w_d2  = (const float*)d_in[27];
    const float* b_d2  = (const float*)d_in[28];
    const float* w_e   = (const float*)d_in[29];
    const float* b_e   = (const float*)d_in[30];
    float* out = (float*)d_out;

    float *qkv, *scores, *abar, *seqr, *bufA, *bufB, *d1o;
    cudaGetSymbolAddress((void**)&qkv,    g_qkv);
    cudaGetSymbolAddress((void**)&scores, g_scores);
    cudaGetSymbolAddress((void**)&abar,   g_abar);
    cudaGetSymbolAddress((void**)&seqr,   g_seqr);
    cudaGetSymbolAddress((void**)&bufA,   g_bufA);
    cudaGetSymbolAddress((void**)&bufB,   g_bufB);
    cudaGetSymbolAddress((void**)&d1o,    g_d1o);

    // opt-in to >48KB dynamic smem (idempotent; not a stream op, graph-capture safe)
    cudaFuncSetAttribute(gemm_tf32x2_k, cudaFuncAttributeMaxDynamicSharedMemorySize, GEMM_SMEM);

    // --- qkv = hs @ w_qkv.T + b_qkv  (tf32x2; M=32768, N=2304, K=768) ---
    gemm_tf32x2_k<<<dim3(2304 / 128, 32768 / 128, 1), 256, GEMM_SMEM>>>(
        hs, HH, 0, 0, w_qkv, HH, 0, 0, b_qkv, qkv, 2304, 0, HH, 1);

    // --- scores[b,h] = q @ k^T  (batched over 2048 heads; M=N=128, K=96) ---
    gemm_tf32x2_k<<<dim3(1, 1, BB * NHH), 256, GEMM_SMEM>>>(
        qkv, 2304, (long)SS * 2304, 96,
        qkv + 768, 2304, (long)SS * 2304, 96,
        nullptr, scores, 128, (long)SS * SS, HDD, NHH);

    // --- softmax row-mean + GEMV -> abar (B, H) ---
    attn_kernel<<<BB * NHH, 128>>>(scores, qkv, abar);

    auto gemm = [&](const float* A, int lda, const float* W, const float* bias,
                    float* C, int N, int K) {
        dim3 grid(N / 128, BB / 128, 1);
        gemm_tf32x2_k<<<grid, 256, GEMM_SMEM>>>(A, lda, 0, 0, W, K, 0, 0, bias, C, N, 0, K, 1);
    };

    // --- seq_repr = abar @ w_out.T + b_out  (exact: mean commutes with linear) ---
    gemm(abar, HH, w_out, b_out, seqr, HH, HH);

    // --- f1 -> f2 -> ctx -> r1 chain ---
    gemm(seqr, HH, w_f1, b_f1, bufA, 1536, HH);
    ln_gelu_k<<<BB, 256>>>(bufA, gf1, bef1, bufB, 1536);

    gemm(bufB, 1536, w_f2, b_f2, bufA, 1536, 1536);
    ln_gelu_k<<<BB, 256>>>(bufA, gf2, bef2, bufB, 1536);

    gemm(bufB, 1536, w_c, b_c, bufA, HH, 1536);
    ln_gelu_k<<<BB, 256>>>(bufA, gc, bec, bufB, HH);

    gemm(bufB, HH, w_r1, b_r1, bufA, 384, HH);
    ln_gelu_k<<<BB, 256>>>(bufA, gr1, ber1, bufB, 384);   // bufB = r1o (256 x 384)

    // --- domain path (cls rows of hidden, lda = S*H) ---
    gemm(hs, SS * HH, w_d1, b_d1, bufA, 384, HH);
    ln_gelu_k<<<BB, 256>>>(bufA, gd1, bed1, d1o, 384);
    head5_kernel<<<BB, 160>>>(d1o, 384, w_d2, b_d2, out + 4352);

    // --- gating softmax + top-2 + expert logits / final logits ---
    gate_kernel<<<BB, 256>>>(bufB, w_r2, b_r2, hs, w_e, b_e, out);

    (void)in_sizes; (void)n_in; (void)out_size;
}

// round 5
// speedup vs baseline: 1.3455x; 1.1729x over previous
#include <cuda_runtime.h>
#include <math.h>
#include <stdint.h>

// ---------------- problem constants ----------------
#define BB 256
#define SS 128
#define HH 768
#define NHH 8
#define HDD 96
// qkv row stride = 3*H = 2304

// ---------------- scratch (static device globals; no runtime alloc) ----------------
__device__ float g_qkv[75497472];      // 32768 * 2304  (302 MB)
__device__ float g_scores[33554432];   // 2048 * 128 * 128 (128 MB)
__device__ float g_abar[BB * HH];
__device__ float g_seqr[BB * HH];
__device__ float g_bufA[BB * 1536];
__device__ float g_bufB[BB * 1536];
__device__ float g_d1o[BB * 384];
__device__ float g_part[4718592];      // split-K partials: up to 12 * 256 * 1536

// ---------------- tf32 helpers ----------------
__device__ __forceinline__ unsigned f2tf(float x) {
    unsigned r;
    asm("cvt.rna.tf32.f32 %0, %1;" : "=r"(r) : "f"(x));
    return r;
}

// ---------------- fused tf32x2 (3-pass) GEMM:  C[m,n] = sum_k A[m,k] * W[n,k] ----------------
// hi = tf32(x), lo = tf32(x - hi); accumulate ah*bl + al*bh + ah*bh (lo*lo dropped).
// Split happens ONCE per element at STS time; inner loop is pure LDS + MMA.
// Block tile 128x128, K-tile 32, 256 threads, warps 2x4, each warp 64x32 (4x4 m16n8k8).
// __launch_bounds__(256,2): 2 CTAs/SM -> 4 warps/SMSP; the load/convert phase of one
// CTA overlaps the LDS/MMA phase of the other (single-buffered smem per CTA).
// z-batch: offA = (z/zdiv)*sA1 + (z%zdiv)*sA2 (same for W); offC = z*sC.
// Split-K reuses this: zdiv=Z, sA2=sW2=Kc, sC=M*N, bias=null -> partials.
__global__ void __launch_bounds__(256, 2) gemm_tf32x2_k(
    const float* __restrict__ A, int lda, long sA1, long sA2,
    const float* __restrict__ W, int ldw, long sW1, long sW2,
    const float* __restrict__ bias, float* __restrict__ C, int ldc, long sC,
    int K, int zdiv)
{
    extern __shared__ float sm[];
    float* Ah = sm;            // 128 x 36 (padded)
    float* Al = sm + 4608;
    float* Bh = sm + 9216;
    float* Bl = sm + 13824;    // total 73728 B

    int z = blockIdx.z;
    const float* Ab = A + (long)(z / zdiv) * sA1 + (long)(z % zdiv) * sA2 + (long)blockIdx.y * 128 * lda;
    const float* Wb = W + (long)(z / zdiv) * sW1 + (long)(z % zdiv) * sW2 + (long)blockIdx.x * 128 * ldw;
    float* Cb = C + (long)z * sC + (long)blockIdx.y * 128 * ldc + blockIdx.x * 128;

    int tid = threadIdx.x, warp = tid >> 5, lane = tid & 31;
    int wm = warp >> 2, wn = warp & 3;     // 2 x 4 warp grid
    int g = lane >> 2, t = lane & 3;       // groupID, threadID_in_group

    // load coordinates: each thread owns one row-half (16 floats) of each operand tile
    int lr = tid >> 1, lh = (tid & 1) * 16;

    float acc[4][4][4];
#pragma unroll
    for (int i = 0; i < 4; i++)
#pragma unroll
        for (int j = 0; j < 4; j++)
#pragma unroll
            for (int e = 0; e < 4; e++) acc[i][j][e] = 0.0f;

    for (int k0 = 0; k0 < K; k0 += 32) {
        // load + split + STS (no register staging: rely on 2-CTA overlap for latency)
        {
            const float* srcA = Ab + (long)lr * lda + k0 + lh;
            const float* srcW = Wb + (long)lr * ldw + k0 + lh;
            int base = lr * 36 + lh;
#pragma unroll
            for (int i = 0; i < 4; i++) {
                float4 v = *(const float4*)(srcA + i * 4);
                float4 h, l;
                h.x = __uint_as_float(f2tf(v.x)); l.x = __uint_as_float(f2tf(v.x - h.x));
                h.y = __uint_as_float(f2tf(v.y)); l.y = __uint_as_float(f2tf(v.y - h.y));
                h.z = __uint_as_float(f2tf(v.z)); l.z = __uint_as_float(f2tf(v.z - h.z));
                h.w = __uint_as_float(f2tf(v.w)); l.w = __uint_as_float(f2tf(v.w - h.w));
                *(float4*)(&Ah[base + i * 4]) = h;
                *(float4*)(&Al[base + i * 4]) = l;
                v = *(const float4*)(srcW + i * 4);
                h.x = __uint_as_float(f2tf(v.x)); l.x = __uint_as_float(f2tf(v.x - h.x));
                h.y = __uint_as_float(f2tf(v.y)); l.y = __uint_as_float(f2tf(v.y - h.y));
                h.z = __uint_as_float(f2tf(v.z)); l.z = __uint_as_float(f2tf(v.z - h.z));
                h.w = __uint_as_float(f2tf(v.w)); l.w = __uint_as_float(f2tf(v.w - h.w));
                *(float4*)(&Bh[base + i * 4]) = h;
                *(float4*)(&Bl[base + i * 4]) = l;
            }
        }
        __syncthreads();

        // pure LDS + MMA inner loop
#pragma unroll
        for (int ks = 0; ks < 4; ks++) {
            int c0 = ks * 8 + t;

            unsigned bhf[4][2], blf[4][2];
#pragma unroll
            for (int nt = 0; nt < 4; nt++) {
                int n0 = (wn * 32 + nt * 8 + g) * 36 + c0;
                bhf[nt][0] = __float_as_uint(Bh[n0]);
                bhf[nt][1] = __float_as_uint(Bh[n0 + 4]);
                blf[nt][0] = __float_as_uint(Bl[n0]);
                blf[nt][1] = __float_as_uint(Bl[n0 + 4]);
            }

#pragma unroll
            for (int mt = 0; mt < 4; mt++) {
                int r0 = (wm * 64 + mt * 16 + g) * 36 + c0;
                unsigned ah[4], al[4];
                ah[0] = __float_as_uint(Ah[r0]);
                ah[1] = __float_as_uint(Ah[r0 + 8 * 36]);
                ah[2] = __float_as_uint(Ah[r0 + 4]);
                ah[3] = __float_as_uint(Ah[r0 + 8 * 36 + 4]);
                al[0] = __float_as_uint(Al[r0]);
                al[1] = __float_as_uint(Al[r0 + 8 * 36]);
                al[2] = __float_as_uint(Al[r0 + 4]);
                al[3] = __float_as_uint(Al[r0 + 8 * 36 + 4]);

#pragma unroll
                for (int nt = 0; nt < 4; nt++) {
                    asm("mma.sync.aligned.m16n8k8.row.col.f32.tf32.tf32.f32 "
                        "{%0,%1,%2,%3},{%4,%5,%6,%7},{%8,%9},{%0,%1,%2,%3};"
                        : "+f"(acc[mt][nt][0]), "+f"(acc[mt][nt][1]),
                          "+f"(acc[mt][nt][2]), "+f"(acc[mt][nt][3])
                        : "r"(ah[0]), "r"(ah[1]), "r"(ah[2]), "r"(ah[3]),
                          "r"(blf[nt][0]), "r"(blf[nt][1]));
                    asm("mma.sync.aligned.m16n8k8.row.col.f32.tf32.tf32.f32 "
                        "{%0,%1,%2,%3},{%4,%5,%6,%7},{%8,%9},{%0,%1,%2,%3};"
                        : "+f"(acc[mt][nt][0]), "+f"(acc[mt][nt][1]),
                          "+f"(acc[mt][nt][2]), "+f"(acc[mt][nt][3])
                        : "r"(al[0]), "r"(al[1]), "r"(al[2]), "r"(al[3]),
                          "r"(bhf[nt][0]), "r"(bhf[nt][1]));
                    asm("mma.sync.aligned.m16n8k8.row.col.f32.tf32.tf32.f32 "
                        "{%0,%1,%2,%3},{%4,%5,%6,%7},{%8,%9},{%0,%1,%2,%3};"
                        : "+f"(acc[mt][nt][0]), "+f"(acc[mt][nt][1]),
                          "+f"(acc[mt][nt][2]), "+f"(acc[mt][nt][3])
                        : "r"(ah[0]), "r"(ah[1]), "r"(ah[2]), "r"(ah[3]),
                          "r"(bhf[nt][0]), "r"(bhf[nt][1]));
                }
            }
        }
        __syncthreads();
    }

    // epilogue: C = acc (+bias)
#pragma unroll
    for (int mt = 0; mt < 4; mt++) {
        int r0 = wm * 64 + mt * 16 + g;
#pragma unroll
        for (int nt = 0; nt < 4; nt++) {
            int c = wn * 32 + nt * 8 + 2 * t;
            float b0 = 0.f, b1 = 0.f;
            if (bias) { b0 = bias[blockIdx.x * 128 + c]; b1 = bias[blockIdx.x * 128 + c + 1]; }
            float* p0 = Cb + (long)r0 * ldc + c;
            float* p1 = Cb + (long)(r0 + 8) * ldc + c;
            p0[0] = acc[mt][nt][0] + b0; p0[1] = acc[mt][nt][1] + b1;
            p1[0] = acc[mt][nt][2] + b0; p1[1] = acc[mt][nt][3] + b1;
        }
    }
}

#define GEMM_SMEM 73728

// ---------------- split-K reduction: C[i] = sum_z part[z][i] + bias[i % N] ----------------
__global__ void reduce_k(const float* __restrict__ part, int Z, long stride,
                         const float* __restrict__ bias, int N,
                         float* __restrict__ C, int total)
{
    int i = blockIdx.x * blockDim.x + threadIdx.x;
    if (i < total) {
        float s = 0.f;
        for (int zz = 0; zz < Z; zz++) s += part[(long)zz * stride + i];
        C[i] = s + bias[i % N];
    }
}

// ---------------- attention: softmax row-mean + GEMV (per head) ----------------
// abar[b, h*96+d] = sum_k ((1/S) sum_s attn[s,k]) * v[k,d]
__global__ void attn_kernel(const float* __restrict__ scores,
                            const float* __restrict__ qkv,
                            float* __restrict__ abar)
{
    __shared__ float wa[4][128];
    int bh = blockIdx.x;
    int b = bh >> 3, h = bh & 7;
    int tid = threadIdx.x, warp = tid >> 5, lane = tid & 31;

#pragma unroll
    for (int j = 0; j < 4; j++) wa[warp][lane + 32 * j] = 0.0f;

    const float* sc = scores + (long)bh * 16384;
    const float scale = 0.10206207261596577f;  // 1/sqrt(96)

    for (int s = warp; s < 128; s += 4) {
        float x0 = sc[s * 128 + lane] * scale;
        float x1 = sc[s * 128 + lane + 32] * scale;
        float x2 = sc[s * 128 + lane + 64] * scale;
        float x3 = sc[s * 128 + lane + 96] * scale;
        float m = fmaxf(fmaxf(x0, x1), fmaxf(x2, x3));
#pragma unroll
        for (int o = 16; o; o >>= 1) m = fmaxf(m, __shfl_xor_sync(0xffffffffu, m, o));
        float e0 = expf(x0 - m), e1 = expf(x1 - m), e2 = expf(x2 - m), e3 = expf(x3 - m);
        float sm = e0 + e1 + e2 + e3;
#pragma unroll
        for (int o = 16; o; o >>= 1) sm += __shfl_xor_sync(0xffffffffu, sm, o);
        float inv = 1.0f / sm;
        wa[warp][lane]      += e0 * inv;
        wa[warp][lane + 32] += e1 * inv;
        wa[warp][lane + 64] += e2 * inv;
        wa[warp][lane + 96] += e3 * inv;
    }
    __syncthreads();
    if (warp == 0) {
#pragma unroll
        for (int j = 0; j < 4; j++) {
            int c = lane + 32 * j;
            wa[0][c] = wa[0][c] + wa[1][c] + wa[2][c] + wa[3][c];
        }
    }
    __syncthreads();

    if (tid < 96) {
        const float* v = qkv + (long)b * SS * 2304 + 1536 + h * 96 + tid;
        float acc = 0.0f;
#pragma unroll 8
        for (int k = 0; k < 128; k++) acc = fmaf(wa[0][k], v[(long)k * 2304], acc);
        abar[b * HH + h * 96 + tid] = acc * (1.0f / 128.0f);
    }
}

// ---------------- fused LayerNorm + exact GELU ----------------
__global__ void ln_gelu_k(const float* __restrict__ in, const float* __restrict__ gm,
                          const float* __restrict__ be, float* __restrict__ out, int N)
{
    int row = blockIdx.x;
    const float* x = in + (long)row * N;
    float* y = out + (long)row * N;
    int tid = threadIdx.x, warp = tid >> 5, lane = tid & 31;

    float s = 0.f, s2 = 0.f;
    for (int i = tid; i < N; i += blockDim.x) { float v = x[i]; s += v; s2 += v * v; }
#pragma unroll
    for (int o = 16; o; o >>= 1) { s += __shfl_xor_sync(0xffffffffu, s, o); s2 += __shfl_xor_sync(0xffffffffu, s2, o); }
    __shared__ float rs[8], rs2[8], sm_mean, sm_rstd;
    if (lane == 0) { rs[warp] = s; rs2[warp] = s2; }
    __syncthreads();
    if (tid == 0) {
        float S = 0.f, S2 = 0.f;
        for (int w = 0; w < 8; w++) { S += rs[w]; S2 += rs2[w]; }
        float mean = S / N;
        float var = S2 / N - mean * mean;
        sm_mean = mean;
        sm_rstd = rsqrtf(var + 1e-5f);
    }
    __syncthreads();
    float mean = sm_mean, rstd = sm_rstd;
    for (int i = tid; i < N; i += blockDim.x) {
        float v = (x[i] - mean) * rstd * gm[i] + be[i];
        y[i] = 0.5f * v * (1.0f + erff(v * 0.70710678118654752f));
    }
}

// ---------------- warp dot helper ----------------
__device__ __forceinline__ float warp_dot(const float* a, const float* b, int n, int lane)
{
    float s = 0.f;
    for (int i = lane; i < n; i += 32) s = fmaf(a[i], b[i], s);
#pragma unroll
    for (int o = 16; o; o >>= 1) s += __shfl_xor_sync(0xffffffffu, s, o);
    return s;
}

// ---------------- small 5-way head (domain logits) ----------------
__global__ void head5_kernel(const float* __restrict__ in, int Kin,
                             const float* __restrict__ w, const float* __restrict__ bias,
                             float* __restrict__ out)
{
    int b = blockIdx.x, warp = threadIdx.x >> 5, lane = threadIdx.x & 31;
    if (warp < 5) {
        float s = warp_dot(in + (long)b * Kin, w + (long)warp * Kin, Kin, lane);
        if (lane == 0) out[b * 5 + warp] = s + bias[warp];
    }
}

// ---------------- gating softmax + top-2 + expert mix ----------------
__global__ void gate_kernel(const float* __restrict__ r1o,
                            const float* __restrict__ w_r2, const float* __restrict__ b_r2,
                            const float* __restrict__ hs,
                            const float* __restrict__ w_e, const float* __restrict__ b_e,
                            float* __restrict__ out)
{
    __shared__ float gl[5], ae[10];
    int b = blockIdx.x, tid = threadIdx.x, warp = tid >> 5, lane = tid & 31;

    if (warp < 5) {
        float s = warp_dot(r1o + (long)b * 384, w_r2 + (long)warp * 384, 384, lane);
        if (lane == 0) gl[warp] = s + b_r2[warp];
    }
    const float* cls = hs + (long)b * SS * HH;
    for (int idx = warp; idx < 10; idx += 8) {
        float s = warp_dot(cls, w_e + (long)idx * HH, HH, lane);
        if (lane == 0) ae[idx] = s + b_e[idx];
    }
    __syncthreads();

    if (tid == 0) {
        float m = gl[0];
        for (int j = 1; j < 5; j++) m = fmaxf(m, gl[j]);
        float e[5], sum = 0.f;
        for (int j = 0; j < 5; j++) { e[j] = expf(gl[j] - m); sum += e[j]; }
        float p[5];
        for (int j = 0; j < 5; j++) { p[j] = e[j] / sum; out[512 + b * 5 + j] = p[j]; }
        // top-2 (first-max on ties, matching jax.lax.top_k)
        int i1 = 0;
        for (int j = 1; j < 5; j++) if (p[j] > p[i1]) i1 = j;
        int i2 = -1;
        for (int j = 0; j < 5; j++) if (j != i1 && (i2 < 0 || p[j] > p[i2])) i2 = j;
        float ps = p[i1] + p[i2];
        float w1 = p[i1] / ps, w2 = p[i2] / ps;
        for (int ee = 0; ee < 5; ee++) {
            bool sel = (ee == i1) || (ee == i2);
            out[1792 + b * 10 + ee * 2 + 0] = sel ? ae[ee * 2 + 0] : 0.0f;
            out[1792 + b * 10 + ee * 2 + 1] = sel ? ae[ee * 2 + 1] : 0.0f;
        }
        out[b * 2 + 0] = w1 * ae[i1 * 2 + 0] + w2 * ae[i2 * 2 + 0];
        out[b * 2 + 1] = w1 * ae[i1 * 2 + 1] + w2 * ae[i2 * 2 + 1];
    }
}

// ---------------- host launcher ----------------
extern "C" void kernel_launch(void* const* d_in, const int* in_sizes, int n_in,
                              void* d_out, int out_size)
{
    const float* hs    = (const float*)d_in[0];
    const float* w_qkv = (const float*)d_in[1];
    const float* b_qkv = (const float*)d_in[2];
    const float* w_out = (const float*)d_in[3];
    const float* b_out = (const float*)d_in[4];
    const float* w_f1  = (const float*)d_in[5];
    const float* b_f1  = (const float*)d_in[6];
    const float* gf1   = (const float*)d_in[7];
    const float* bef1  = (const float*)d_in[8];
    const float* w_f2  = (const float*)d_in[9];
    const float* b_f2  = (const float*)d_in[10];
    const float* gf2   = (const float*)d_in[11];
    const float* bef2  = (const float*)d_in[12];
    const float* w_c   = (const float*)d_in[13];
    const float* b_c   = (const float*)d_in[14];
    const float* gc    = (const float*)d_in[15];
    const float* bec   = (const float*)d_in[16];
    const float* w_r1  = (const float*)d_in[17];
    const float* b_r1  = (const float*)d_in[18];
    const float* gr1   = (const float*)d_in[19];
    const float* ber1  = (const float*)d_in[20];
    const float* w_r2  = (const float*)d_in[21];
    const float* b_r2  = (const float*)d_in[22];
    const float* w_d1  = (const float*)d_in[23];
    const float* b_d1  = (const float*)d_in[24];
    const float* gd1   = (const float*)d_in[25];
    const float* bed1  = (const float*)d_in[26];
    const float* w_d2  = (const float*)d_in[27];
    const float* b_d2  = (const float*)d_in[28];
    const float* w_e   = (const float*)d_in[29];
    const float* b_e   = (const float*)d_in[30];
    float* out = (float*)d_out;

    float *qkv, *scores, *abar, *seqr, *bufA, *bufB, *d1o, *part;
    cudaGetSymbolAddress((void**)&qkv,    g_qkv);
    cudaGetSymbolAddress((void**)&scores, g_scores);
    cudaGetSymbolAddress((void**)&abar,   g_abar);
    cudaGetSymbolAddress((void**)&seqr,   g_seqr);
    cudaGetSymbolAddress((void**)&bufA,   g_bufA);
    cudaGetSymbolAddress((void**)&bufB,   g_bufB);
    cudaGetSymbolAddress((void**)&d1o,    g_d1o);
    cudaGetSymbolAddress((void**)&part,   g_part);

    // opt-in to >48KB dynamic smem (idempotent; graph-capture safe)
    cudaFuncSetAttribute(gemm_tf32x2_k, cudaFuncAttributeMaxDynamicSharedMemorySize, GEMM_SMEM);

    // --- qkv = hs @ w_qkv.T + b_qkv  (tf32x2; M=32768, N=2304, K=768) ---
    gemm_tf32x2_k<<<dim3(2304 / 128, 32768 / 128, 1), 256, GEMM_SMEM>>>(
        hs, HH, 0, 0, w_qkv, HH, 0, 0, b_qkv, qkv, 2304, 0, HH, 1);

    // --- scores[b,h] = q @ k^T  (batched over 2048 heads; M=N=128, K=96) ---
    gemm_tf32x2_k<<<dim3(1, 1, BB * NHH), 256, GEMM_SMEM>>>(
        qkv, 2304, (long)SS * 2304, 96,
        qkv + 768, 2304, (long)SS * 2304, 96,
        nullptr, scores, 128, (long)SS * SS, HDD, NHH);

    // --- softmax row-mean + GEMV -> abar (B, H) ---
    attn_kernel<<<BB * NHH, 128>>>(scores, qkv, abar);

    // split-K GEMM for the B=256 chain: Kc=128 chunks -> Z * (N/128) * 2 blocks
    auto gemmsk = [&](const float* A, int lda, const float* W, const float* bias,
                      float* Cfinal, int N, int K) {
        const int Kc = 128;
        int Z = K / Kc;
        dim3 grid(N / 128, BB / 128, Z);
        gemm_tf32x2_k<<<grid, 256, GEMM_SMEM>>>(
            A, lda, 0, Kc, W, K, 0, Kc, nullptr, part, N, (long)BB * N, Kc, Z);
        int total = BB * N;
        reduce_k<<<(total + 255) / 256, 256>>>(part, Z, (long)BB * N, bias, N, Cfinal, total);
    };

    // --- seq_repr = abar @ w_out.T + b_out  (exact: mean commutes with linear) ---
    gemmsk(abar, HH, w_out, b_out, seqr, HH, HH);

    // --- f1 -> f2 -> ctx -> r1 chain ---
    gemmsk(seqr, HH, w_f1, b_f1, bufA, 1536, HH);
    ln_gelu_k<<<BB, 256>>>(bufA, gf1, bef1, bufB, 1536);

    gemmsk(bufB, 1536, w_f2, b_f2, bufA, 1536, 1536);
    ln_gelu_k<<<BB, 256>>>(bufA, gf2, bef2, bufB, 1536);

    gemmsk(bufB, 1536, w_c, b_c, bufA, HH, 1536);
    ln_gelu_k<<<BB, 256>>>(bufA, gc, bec, bufB, HH);

    gemmsk(bufB, HH, w_r1, b_r1, bufA, 384, HH);
    ln_gelu_k<<<BB, 256>>>(bufA, gr1, ber1, bufB, 384);   // bufB = r1o (256 x 384)

    // --- domain path (cls rows of hidden, lda = S*H) ---
    gemmsk(hs, SS * HH, w_d1, b_d1, bufA, 384, HH);
    ln_gelu_k<<<BB, 256>>>(bufA, gd1, bed1, d1o, 384);
    head5_kernel<<<BB, 160>>>(d1o, 384, w_d2, b_d2, out + 4352);

    // --- gating softmax + top-2 + expert logits / final logits ---
    gate_kernel<<<BB, 256>>>(bufB, w_r2, b_r2, hs, w_e, b_e, out);

    (void)in_sizes; (void)n_in; (void)out_size;
}